// round 15
// baseline (speedup 1.0000x reference)
#include <cuda_runtime.h>

// out[i,:] = 40320 * ( sum_j relu(x @ W1 + b1)[j,:] @ W2 + 9*b2 ), broadcast to 9 rows.
// N=9, D=512, H=32, C=4.
//
// 9 blocks (one per row) x 512 threads. Thread t = kc*8 + hq:
//   kc in [0,64): 8-wide k-chunk;  hq in [0,8): quad of hidden units.
// Each thread: 8 float4 W1 loads + 2 float4 x loads (one exposed latency round),
// 32 FMAs into 4 accumulators. kc-reduce: 2 xor-shuffles -> smem -> warp 0.
//
// Cross-block: RED-accumulate into g_s[32] (R12 structure, the fastest measured),
// with the last block's critical path trimmed:
//   - W2/b2 prefetched into registers in EVERY block's warp 0 (overlaps the body)
//   - gather via ld.global.cg + plain store reset (cheaper than atomicExch)
//   - W2 reduce via shuffles (no shared-memory bounce)
// g_count self-resets each call -> graph-replay deterministic.

#define D_DIM  512
#define H_DIM  32
#define C_DIM  4
#define N_ROWS 9
#define NT     512
#define KLEN   8
#define NWARP  16

__device__ float        g_s[H_DIM];   // zero at load; consumed+reset every call
__device__ unsigned int g_count;      // zero at load; reset every call

__global__ __launch_bounds__(NT)
void symnet_fused(const float* __restrict__ x,
                  const float* __restrict__ W1,
                  const float* __restrict__ b1,
                  const float* __restrict__ W2,
                  const float* __restrict__ b2,
                  float* __restrict__ out) {
    const int r    = blockIdx.x;        // row 0..8
    const int t    = threadIdx.x;       // 0..511
    const int hq   = t & 7;             // h quad
    const int kc   = t >> 3;            // 0..63
    const int w    = t >> 5;            // warp 0..15
    const int lane = t & 31;

    const float4* __restrict__ x4  = (const float4*)(x + r * D_DIM) + kc * (KLEN / 4);
    const float4* __restrict__ W14 = (const float4*)W1;   // quad (k*8 + hq)

    // ---- warp 0: prefetch epilogue operands early (off the critical tail) ----
    float w2p[4];
    float b2v = 0.0f, b1v = 0.0f;
    if (t < H_DIM) {
        const int c  = lane & 3;
        const int h0 = lane >> 2;
        #pragma unroll
        for (int j = 0; j < 4; ++j)
            w2p[j] = W2[(h0 + 8 * j) * C_DIM + c];
        b2v = b2[c];
        b1v = b1[lane];
    }

    // ---- batched loads: 2 x-quads + 8 W1-quads, all independent ----
    float4 xa = x4[0];
    float4 xb = x4[1];
    float4 wq[KLEN];
    const int k0 = kc * KLEN;
    #pragma unroll
    for (int i = 0; i < KLEN; ++i)
        wq[i] = W14[(k0 + i) * 8 + hq];

    float4 acc = make_float4(0.f, 0.f, 0.f, 0.f);
    const float xs[KLEN] = {xa.x, xa.y, xa.z, xa.w, xb.x, xb.y, xb.z, xb.w};
    #pragma unroll
    for (int i = 0; i < KLEN; ++i) {
        acc.x = fmaf(xs[i], wq[i].x, acc.x);
        acc.y = fmaf(xs[i], wq[i].y, acc.y);
        acc.z = fmaf(xs[i], wq[i].z, acc.z);
        acc.w = fmaf(xs[i], wq[i].w, acc.w);
    }

    // ---- combine the 4 kc-chunks inside each warp (lane = kcl*8 + hq) ----
    #pragma unroll
    for (int off = 8; off <= 16; off <<= 1) {
        acc.x += __shfl_xor_sync(0xffffffffu, acc.x, off);
        acc.y += __shfl_xor_sync(0xffffffffu, acc.y, off);
        acc.z += __shfl_xor_sync(0xffffffffu, acc.z, off);
        acc.w += __shfl_xor_sync(0xffffffffu, acc.w, off);
    }

    __shared__ float4 sh[NWARP][8];     // per-warp partial hidden quads
    if (lane < 8) sh[w][lane] = acc;
    __syncthreads();

    // ---- warp 0 finishes this row ----
    if (t < H_DIM) {
        const int h = t;
        const float* shf = (const float*)sh;      // [16][32] floats: shf[warp*32 + h]
        float z = b1v;
        #pragma unroll
        for (int j = 0; j < NWARP; ++j)
            z += shf[j * H_DIM + h];
        z = fmaxf(z, 0.0f);

        atomicAdd(&g_s[h], z);          // RED accumulate (no return trip)
        __threadfence();                // publish before counting

        unsigned old = 0;
        if (t == 0) old = atomicAdd(&g_count, 1u);
        old = __shfl_sync(0xffffffffu, old, 0);

        if (old == N_ROWS - 1) {
            // Last block: read the accumulated hidden sums. L1 was flushed at
            // launch and atomics never populate it, so .cg reads see fresh L2.
            float sv;
            asm volatile("ld.global.cg.f32 %0, [%1];"
                         : "=f"(sv) : "l"(&g_s[h]));
            g_s[h] = 0.0f;              // reset for next replay (ordered by kernel end)

            // lane l: c = l&3, h0 = l>>2; needs sv[h0 + 8j], j<4 -- lane h
            // holds sv[h], so fetch via shuffles (no smem bounce).
            const int h0 = lane >> 2;
            float v = 0.0f;
            #pragma unroll
            for (int j = 0; j < 4; ++j) {
                const float svj = __shfl_sync(0xffffffffu, sv, h0 + 8 * j);
                v = fmaf(svj, w2p[j], v);
            }
            // Sum across the 8 lanes sharing c (lane bits 2..4 = h0):
            v += __shfl_xor_sync(0xffffffffu, v, 4);
            v += __shfl_xor_sync(0xffffffffu, v, 8);
            v += __shfl_xor_sync(0xffffffffu, v, 16);

            const float tot = 40320.0f * (v + 9.0f * b2v);

            // 36 outputs: out[i*4+c]. Lane l covers out[l]; lanes 0..3 also out[32..35].
            out[lane] = tot;
            if (lane < C_DIM) out[H_DIM + lane] = tot;

            if (t == 0) atomicExch(&g_count, 0u);    // reset for next replay
        }
    }
}

extern "C" void kernel_launch(void* const* d_in, const int* in_sizes, int n_in,
                              void* d_out, int out_size) {
    // metadata order: x, W1, b1, W2, b2, perms
    const float* x  = (const float*)d_in[0];
    const float* W1 = (const float*)d_in[1];
    const float* b1 = (const float*)d_in[2];
    const float* W2 = (const float*)d_in[3];
    const float* b2 = (const float*)d_in[4];
    // perms unused: each source row appears (N-1)! = 40320 times at every
    // output position, so the permutation sum collapses analytically.
    float* out = (float*)d_out;

    symnet_fused<<<N_ROWS, NT>>>(x, W1, b1, W2, b2, out);
}

// round 17
// speedup vs baseline: 1.2488x; 1.2488x over previous
#include <cuda_runtime.h>

// out[i,:] = 40320 * ( sum_j relu(x @ W1 + b1)[j,:] @ W2 + 9*b2 ), broadcast to 9 rows.
// N=9, D=512, H=32, C=4.
//
// 9 blocks (one per row) x 512 threads. Thread t = kc*8 + hq:
//   kc in [0,64): 8-wide k-chunk;  hq in [0,8): quad of hidden units.
// Each thread: 8 float4 W1 loads + 2 float4 x loads (one exposed latency round),
// 32 FMAs into 4 accumulators. kc-reduce: 2 xor-shuffles -> smem -> warp 0.
//
// Cross-block tail (R12 structure, best bench measured):
//   RED-accumulate into g_s[32] -> threadfence -> counter -> last block
//   atomicExch-gathers (read+reset in ONE op) and finalizes.
// Plus the two ncu-validated trims from R15:
//   - W2/b1/b2 prefetched into registers in every block's warp 0 (pure overlap)
//   - W2 reduce via shuffles (no shared-memory bounce in the epilogue)
// g_count self-resets each call -> graph-replay deterministic.

#define D_DIM  512
#define H_DIM  32
#define C_DIM  4
#define N_ROWS 9
#define NT     512
#define KLEN   8
#define NWARP  16

__device__ float        g_s[H_DIM];   // zero at load; consumed+reset every call
__device__ unsigned int g_count;      // zero at load; reset every call

__global__ __launch_bounds__(NT)
void symnet_fused(const float* __restrict__ x,
                  const float* __restrict__ W1,
                  const float* __restrict__ b1,
                  const float* __restrict__ W2,
                  const float* __restrict__ b2,
                  float* __restrict__ out) {
    const int r    = blockIdx.x;        // row 0..8
    const int t    = threadIdx.x;       // 0..511
    const int hq   = t & 7;             // h quad
    const int kc   = t >> 3;            // 0..63
    const int w    = t >> 5;            // warp 0..15
    const int lane = t & 31;

    const float4* __restrict__ x4  = (const float4*)(x + r * D_DIM) + kc * (KLEN / 4);
    const float4* __restrict__ W14 = (const float4*)W1;   // quad (k*8 + hq)

    // ---- warp 0: prefetch epilogue operands early (off the critical tail) ----
    float w2p[4];
    float b2v = 0.0f, b1v = 0.0f;
    if (t < H_DIM) {
        const int c  = lane & 3;
        const int h0 = lane >> 2;
        #pragma unroll
        for (int j = 0; j < 4; ++j)
            w2p[j] = W2[(h0 + 8 * j) * C_DIM + c];
        b2v = b2[c];
        b1v = b1[lane];
    }

    // ---- batched loads: 2 x-quads + 8 W1-quads, all independent ----
    float4 xa = x4[0];
    float4 xb = x4[1];
    float4 wq[KLEN];
    const int k0 = kc * KLEN;
    #pragma unroll
    for (int i = 0; i < KLEN; ++i)
        wq[i] = W14[(k0 + i) * 8 + hq];

    float4 acc = make_float4(0.f, 0.f, 0.f, 0.f);
    const float xs[KLEN] = {xa.x, xa.y, xa.z, xa.w, xb.x, xb.y, xb.z, xb.w};
    #pragma unroll
    for (int i = 0; i < KLEN; ++i) {
        acc.x = fmaf(xs[i], wq[i].x, acc.x);
        acc.y = fmaf(xs[i], wq[i].y, acc.y);
        acc.z = fmaf(xs[i], wq[i].z, acc.z);
        acc.w = fmaf(xs[i], wq[i].w, acc.w);
    }

    // ---- combine the 4 kc-chunks inside each warp (lane = kcl*8 + hq) ----
    #pragma unroll
    for (int off = 8; off <= 16; off <<= 1) {
        acc.x += __shfl_xor_sync(0xffffffffu, acc.x, off);
        acc.y += __shfl_xor_sync(0xffffffffu, acc.y, off);
        acc.z += __shfl_xor_sync(0xffffffffu, acc.z, off);
        acc.w += __shfl_xor_sync(0xffffffffu, acc.w, off);
    }

    __shared__ float4 sh[NWARP][8];     // per-warp partial hidden quads
    if (lane < 8) sh[w][lane] = acc;
    __syncthreads();

    // ---- warp 0 finishes this row ----
    if (t < H_DIM) {
        const int h = t;
        const float* shf = (const float*)sh;      // [16][32] floats: shf[warp*32 + h]
        float z = b1v;
        #pragma unroll
        for (int j = 0; j < NWARP; ++j)
            z += shf[j * H_DIM + h];
        z = fmaxf(z, 0.0f);

        atomicAdd(&g_s[h], z);          // RED accumulate (no return trip)
        __threadfence();                // publish before counting

        unsigned old = 0;
        if (t == 0) old = atomicAdd(&g_count, 1u);
        old = __shfl_sync(0xffffffffu, old, 0);

        if (old == N_ROWS - 1) {
            // Last block: consume + reset the accumulator in ONE atomic op.
            const float sv = atomicExch(&g_s[h], 0.0f);  // sum over rows of relu-hidden

            // lane l: c = l&3, h0 = l>>2; needs sv[h0 + 8j], j<4 -- lane h
            // holds sv[h], so fetch via shuffles (no smem bounce).
            const int h0 = lane >> 2;
            float v = 0.0f;
            #pragma unroll
            for (int j = 0; j < 4; ++j) {
                const float svj = __shfl_sync(0xffffffffu, sv, h0 + 8 * j);
                v = fmaf(svj, w2p[j], v);
            }
            // Sum across the 8 lanes sharing c (lane bits 2..4 = h0):
            v += __shfl_xor_sync(0xffffffffu, v, 4);
            v += __shfl_xor_sync(0xffffffffu, v, 8);
            v += __shfl_xor_sync(0xffffffffu, v, 16);

            const float tot = 40320.0f * (v + 9.0f * b2v);

            // 36 outputs: out[i*4+c]. Lane l covers out[l]; lanes 0..3 also out[32..35].
            out[lane] = tot;
            if (lane < C_DIM) out[H_DIM + lane] = tot;

            if (t == 0) atomicExch(&g_count, 0u);    // reset for next replay
        }
    }
}

extern "C" void kernel_launch(void* const* d_in, const int* in_sizes, int n_in,
                              void* d_out, int out_size) {
    // metadata order: x, W1, b1, W2, b2, perms
    const float* x  = (const float*)d_in[0];
    const float* W1 = (const float*)d_in[1];
    const float* b1 = (const float*)d_in[2];
    const float* W2 = (const float*)d_in[3];
    const float* b2 = (const float*)d_in[4];
    // perms unused: each source row appears (N-1)! = 40320 times at every
    // output position, so the permutation sum collapses analytically.
    float* out = (float*)d_out;

    symnet_fused<<<N_ROWS, NT>>>(x, W1, b1, W2, b2, out);
}